// round 1
// baseline (speedup 1.0000x reference)
#include <cuda_runtime.h>

// MaskedWeight: B=256, DIM=16, H_IN=H_OUT=32, IN_F=OUT_F=512
// Single pass over the lower-block-triangular prefix of hyper_w per sample:
// accumulate unnormalized matvec + Frobenius norm + diag logsumexp, then
// finalize with the per-sample scalar normalization.

#define NB 256
#define OUTF 512
#define INF 512

__global__ __launch_bounds__(512, 2)
void mw_kernel(const float* __restrict__ inputs,     // [B, 512]
               const float* __restrict__ hyper_w,    // [B, 512, 512]
               const float* __restrict__ hyper_b,    // [B, 512]
               const float* __restrict__ lgc,        // [B, 16, 32, 1]
               const float* __restrict__ sfp,        // [1]
               float* __restrict__ out)              // [B*512 outputs | B*512 log_det]
{
    const int b    = blockIdx.x;
    const int tid  = threadIdx.x;
    const int warp = tid >> 5;
    const int lane = tid & 31;

    __shared__ __align__(16) float x_s[INF];
    __shared__ float lgc_s[512];
    __shared__ float y_s[OUTF];
    __shared__ float lse_s[OUTF];
    __shared__ float f2_red[16];

    const float* hw = hyper_w + (size_t)b * (OUTF * INF);

    x_s[tid]   = inputs[b * INF + tid];
    lgc_s[tid] = lgc[b * 512 + tid];   // [d, hi] flattened: d*32 + hi
    __syncthreads();

    const float4* x4 = reinterpret_cast<const float4*>(x_s);
    float f2 = 0.0f;   // per-lane partial Frobenius accumulation across all rows

    #pragma unroll 1
    for (int o = warp; o < OUTF; o += 16) {
        const int rb = o >> 5;                       // block row id = d
        const float*  row  = hw + (size_t)o * INF;
        const float4* row4 = reinterpret_cast<const float4*>(row);

        float y = 0.0f;

        // Strictly-lower blocks: columns [0, rb*32), identity mask (w = hw)
        const int n4 = rb << 3;                      // rb*32/4 float4 elems
        for (int i4 = lane; i4 < n4; i4 += 32) {
            float4 v  = row4[i4];
            float4 xv = x4[i4];
            y  = fmaf(v.x, xv.x, y);  f2 = fmaf(v.x, v.x, f2);
            y  = fmaf(v.y, xv.y, y);  f2 = fmaf(v.y, v.y, f2);
            y  = fmaf(v.z, xv.z, y);  f2 = fmaf(v.z, v.z, f2);
            y  = fmaf(v.w, xv.w, y);  f2 = fmaf(v.w, v.w, f2);
        }

        // Diagonal block: columns [rb*32, rb*32+32), w = exp(hw). lane == hi.
        const int nd = rb << 5;
        float v = row[nd + lane];
        float e = __expf(v);
        y  = fmaf(e, x_s[nd + lane], y);
        f2 = fmaf(e, e, f2);

        // logsumexp over hi of (hw_diag + lgc[d, hi])
        float t = v + lgc_s[nd + lane];

        // warp reductions
        #pragma unroll
        for (int s = 16; s; s >>= 1) y += __shfl_xor_sync(0xffffffffu, y, s);
        float m = t;
        #pragma unroll
        for (int s = 16; s; s >>= 1) m = fmaxf(m, __shfl_xor_sync(0xffffffffu, m, s));
        float se = __expf(t - m);
        #pragma unroll
        for (int s = 16; s; s >>= 1) se += __shfl_xor_sync(0xffffffffu, se, s);

        if (lane == 0) {
            y_s[o]   = y;
            lse_s[o] = m + __logf(se);
        }
    }

    // Reduce Frobenius norm: lanes -> warp slot -> all threads
    #pragma unroll
    for (int s = 16; s; s >>= 1) f2 += __shfl_xor_sync(0xffffffffu, f2, s);
    if (lane == 0) f2_red[warp] = f2;
    __syncthreads();

    float F2 = 0.0f;
    #pragma unroll
    for (int w = 0; w < 16; w++) F2 += f2_red[w];

    const float sf   = sfp[0];
    const float inv  = __expf(sf) * rsqrtf(F2);
    const float base = sf - 0.5f * __logf(F2);

    // outputs[b, o] — thread tid handles o = tid
    out[b * OUTF + tid] = fmaf(y_s[tid], inv, hyper_b[b * OUTF + tid]);
    // out_log_det[b, d, ho, 0] with d = o>>5, ho = o&31 -> flat index o
    out[NB * OUTF + b * 512 + tid] = base + lse_s[tid];
}

extern "C" void kernel_launch(void* const* d_in, const int* in_sizes, int n_in,
                              void* d_out, int out_size) {
    const float* inputs  = (const float*)d_in[0];
    const float* hyper_w = (const float*)d_in[1];
    const float* hyper_b = (const float*)d_in[2];
    const float* lgc     = (const float*)d_in[3];
    const float* sf      = (const float*)d_in[4];
    mw_kernel<<<NB, 512>>>(inputs, hyper_w, hyper_b, lgc, sf, (float*)d_out);
}

// round 3
// speedup vs baseline: 1.9886x; 1.9886x over previous
#include <cuda_runtime.h>

// MaskedWeight: B=256, DIM=16, H_IN=H_OUT=32, IN_F=OUT_F=512
// Pass 1 (grid B*8, 256 thr): stream lower-block-triangular prefix of hyper_w.
//   Each warp handles balanced row PAIRS (rb, 15-rb): combined off-diag span is
//   always 120 float4 -> fixed 4-iteration unrolled loop, 4 LDG.128 in flight.
//   Writes y_raw, lse per row and per-CTA partial Frobenius norm to scratch.
// Pass 2 (grid B, 512 thr): reduce F2 partials, finalize outputs + log_det.

#define NB 256
#define OUTF 512
#define INF 512

__device__ float g_yraw[NB * OUTF];
__device__ float g_lse[NB * OUTF];
__device__ float g_f2[NB * 8];

__global__ __launch_bounds__(256, 6)
void mw_pass1(const float* __restrict__ inputs,     // [B, 512]
              const float* __restrict__ hyper_w,    // [B, 512, 512]
              const float* __restrict__ lgc)        // [B, 16, 32, 1]
{
    const int cta  = blockIdx.x;
    const int b    = cta >> 3;
    const int s    = cta & 7;
    const int tid  = threadIdx.x;
    const int warp = tid >> 5;
    const int lane = tid & 31;
    const int g    = (s << 3) + warp;        // global warp id within sample, 0..63

    __shared__ __align__(16) float x_s[INF];
    __shared__ float lgc_s[512];
    __shared__ float f2_red[8];

    x_s[tid]         = inputs[b * INF + tid];
    x_s[tid + 256]   = inputs[b * INF + tid + 256];
    lgc_s[tid]       = lgc[b * 512 + tid];
    lgc_s[tid + 256] = lgc[b * 512 + tid + 256];
    __syncthreads();

    const float*  hw = hyper_w + (size_t)b * (OUTF * INF);
    const float4* x4 = reinterpret_cast<const float4*>(x_s);

    const int colA = g & 31;
    const int rb0  = g >> 5;                  // 0 or 1
    float f2 = 0.0f;

    #pragma unroll
    for (int k = 0; k < 4; k++) {
        const int rbA = rb0 + 2 * k;          // 0..7
        const int rbB = 15 - rbA;             // 15..8
        const int oA  = (rbA << 5) + colA;
        const int oB  = (rbB << 5) + colA;
        const float4* rowA4 = reinterpret_cast<const float4*>(hw + (size_t)oA * INF);
        const float4* rowB4 = reinterpret_cast<const float4*>(hw + (size_t)oB * INF);
        const int n4a = rbA << 3;             // off-diag float4 count of row A (<=56)
        // combined off-diag span = (rbA + rbB)*8 = 120 float4, always.

        float ya = 0.0f, yb = 0.0f;
        #pragma unroll
        for (int j = 0; j < 4; j++) {
            const int i4 = lane + 32 * j;
            if (i4 < 120) {
                const bool inA = (i4 < n4a);
                const int  idx = inA ? i4 : (i4 - n4a);
                const float4 v  = inA ? rowA4[i4] : rowB4[idx];
                const float4 xv = x4[idx];
                float dot = v.x * xv.x;
                dot = fmaf(v.y, xv.y, dot);
                dot = fmaf(v.z, xv.z, dot);
                dot = fmaf(v.w, xv.w, dot);
                f2  = fmaf(v.x, v.x, f2);
                f2  = fmaf(v.y, v.y, f2);
                f2  = fmaf(v.z, v.z, f2);
                f2  = fmaf(v.w, v.w, f2);
                if (inA) ya += dot; else yb += dot;
            }
        }

        // Diagonal blocks: w = exp(hw). lane == hi.
        const int dA = rbA << 5;              // col base of diag block A (== d*32)
        const int dB = rbB << 5;
        const float vA = (hw + (size_t)oA * INF)[dA + lane];
        const float vB = (hw + (size_t)oB * INF)[dB + lane];
        const float eA = __expf(vA);
        const float eB = __expf(vB);
        ya = fmaf(eA, x_s[dA + lane], ya);
        yb = fmaf(eB, x_s[dB + lane], yb);
        f2 = fmaf(eA, eA, f2);
        f2 = fmaf(eB, eB, f2);

        // logsumexp over hi of (hw_diag + lgc[d, hi]) for both rows
        float tA = vA + lgc_s[dA + lane];
        float tB = vB + lgc_s[dB + lane];

        #pragma unroll
        for (int sh = 16; sh; sh >>= 1) {
            ya += __shfl_xor_sync(0xffffffffu, ya, sh);
            yb += __shfl_xor_sync(0xffffffffu, yb, sh);
        }
        float mA = tA, mB = tB;
        #pragma unroll
        for (int sh = 16; sh; sh >>= 1) {
            mA = fmaxf(mA, __shfl_xor_sync(0xffffffffu, mA, sh));
            mB = fmaxf(mB, __shfl_xor_sync(0xffffffffu, mB, sh));
        }
        float sA = __expf(tA - mA);
        float sB = __expf(tB - mB);
        #pragma unroll
        for (int sh = 16; sh; sh >>= 1) {
            sA += __shfl_xor_sync(0xffffffffu, sA, sh);
            sB += __shfl_xor_sync(0xffffffffu, sB, sh);
        }

        if (lane == 0) {
            g_yraw[b * OUTF + oA] = ya;
            g_lse [b * OUTF + oA] = mA + __logf(sA);
        } else if (lane == 1) {
            g_yraw[b * OUTF + oB] = yb;
            g_lse [b * OUTF + oB] = mB + __logf(sB);
        }
    }

    // per-CTA Frobenius partial
    #pragma unroll
    for (int sh = 16; sh; sh >>= 1) f2 += __shfl_xor_sync(0xffffffffu, f2, sh);
    if (lane == 0) f2_red[warp] = f2;
    __syncthreads();
    if (tid == 0) {
        float t = 0.0f;
        #pragma unroll
        for (int w = 0; w < 8; w++) t += f2_red[w];
        g_f2[b * 8 + s] = t;
    }
}

__global__ __launch_bounds__(512)
void mw_pass2(const float* __restrict__ hyper_b,    // [B, 512]
              const float* __restrict__ sfp,        // [1]
              float* __restrict__ out)              // [B*512 outputs | B*512 log_det]
{
    const int b   = blockIdx.x;
    const int tid = threadIdx.x;

    float F2 = 0.0f;
    #pragma unroll
    for (int i = 0; i < 8; i++) F2 += g_f2[b * 8 + i];

    const float sf   = sfp[0];
    const float inv  = __expf(sf) * rsqrtf(F2);
    const float base = sf - 0.5f * __logf(F2);

    out[b * OUTF + tid] = fmaf(g_yraw[b * OUTF + tid], inv, hyper_b[b * OUTF + tid]);
    out[NB * OUTF + b * 512 + tid] = base + g_lse[b * 512 + tid];
}

extern "C" void kernel_launch(void* const* d_in, const int* in_sizes, int n_in,
                              void* d_out, int out_size) {
    const float* inputs  = (const float*)d_in[0];
    const float* hyper_w = (const float*)d_in[1];
    const float* hyper_b = (const float*)d_in[2];
    const float* lgc     = (const float*)d_in[3];
    const float* sf      = (const float*)d_in[4];
    mw_pass1<<<NB * 8, 256>>>(inputs, hyper_w, lgc);
    mw_pass2<<<NB, 512>>>(hyper_b, sf, (float*)d_out);
}